// round 14
// baseline (speedup 1.0000x reference)
#include <cuda_runtime.h>
#include <math.h>
#include <stdint.h>

#define BATCH 32768
#define BM 64

// Pre-packed tf32 weights, fragment-quad-interleaved:
// LSTM: [ni][s16][half][g][cp][q][e4]  (stage = 8192 words)
// FF:   [ni][s16][half][g][cp][q][e4]  (stage = 4096 words)
__device__ __align__(1024) unsigned g_wpack[1048576];

__device__ __forceinline__ unsigned f2tf32(float v) {
    unsigned r;
    asm("cvt.rna.tf32.f32 %0, %1;" : "=r"(r) : "f"(v));
    return r;
}
__device__ __forceinline__ void mma8(float* d, const unsigned* a, const unsigned* b) {
    asm volatile(
        "mma.sync.aligned.m16n8k8.row.col.f32.tf32.tf32.f32 "
        "{%0,%1,%2,%3}, {%4,%5,%6,%7}, {%8,%9}, {%0,%1,%2,%3};\n"
        : "+f"(d[0]), "+f"(d[1]), "+f"(d[2]), "+f"(d[3])
        : "r"(a[0]), "r"(a[1]), "r"(a[2]), "r"(a[3]), "r"(b[0]), "r"(b[1]));
}
__device__ __forceinline__ float sigf(float x) { return 1.0f / (1.0f + __expf(-x)); }

// ---------- pack kernels: fp32 -> tf32(RNA), MMA-fragment quad layout ----------
__global__ void pack_lstm(int dst, const float* __restrict__ w0, const float* __restrict__ w1,
                          const float* __restrict__ w2, const float* __restrict__ w3,
                          int NS, int total)
{
    int t = blockIdx.x * 256 + threadIdx.x;
    if (t >= total) return;
    int e = t & 3, q = (t >> 2) & 3, cp = (t >> 4) & 63, g = (t >> 10) & 3, half = (t >> 12) & 1;
    int r = t >> 13, s = r % NS, ni = r / NS;
    int col = ni * 128 + (cp >> 3) * 16 + (cp & 7) + ((e >> 1) << 3);
    int k = s * 16 + half * 8 + q + ((e & 1) << 2);
    const float* w = (g == 0) ? w0 : (g == 1) ? w1 : (g == 2) ? w2 : w3;
    g_wpack[dst + t] = f2tf32(w[(long)k * 256 + col]);
}
__global__ void pack_ff(int dst, const float* __restrict__ fw, int total)
{
    int t = blockIdx.x * 256 + threadIdx.x;
    if (t >= total) return;
    int e = t & 3, q = (t >> 2) & 3, cp = (t >> 4) & 31, g = (t >> 9) & 3, half = (t >> 11) & 1;
    int r = t >> 12, s = r & 15, ni = r >> 4;
    int col = ni * 256 + g * 64 + (cp >> 3) * 16 + (cp & 7) + ((e >> 1) << 3);
    int k = s * 16 + half * 8 + q + ((e & 1) << 2);
    g_wpack[dst + t] = f2tf32(fw[(long)k * 768 + col]);
}

// MODE 0: LSTM layer (16 warps 2m x 8n, warp tile m32 x n16 x 4 gates)
// MODE 1: FF head    (16 warps 4m x 4n, warp tile m16 x n16 x 4 heads)
template <int MODE>
__global__ void __launch_bounds__(512, 1)
fused_kernel(int K, int NS, int NITER, int wbase, int KA, int lda,
             const float* __restrict__ srcA, const float* __restrict__ srcB,
             const float* __restrict__ b0, const float* __restrict__ b1,
             const float* __restrict__ b2, const float* __restrict__ b3,
             const float* __restrict__ state_in, float* __restrict__ new_state,
             float* __restrict__ means, float* __restrict__ devs,
             float* __restrict__ mult)
{
    constexpr int MT   = (MODE == 0) ? 2 : 1;
    constexpr int WSTG = (MODE == 0) ? 8192 : 4096;   // words per k16 stage
    constexpr int GSTG = (MODE == 0) ? 1024 : 512;    // words per gate per k8
    constexpr int CPW  = WSTG / 512;                  // words copied per thread

    extern __shared__ unsigned sm[];
    const int XP = 2 * K + 16;            // X pitch per rowpair (== 16 mod 32 words)
    unsigned* xs  = sm;                   // X: [rp=32][XP]
    unsigned* wsm = sm + 32 * XP;         // W ring: 2 x WSTG

    const int tid  = threadIdx.x;
    const int lane = tid & 31, wid = tid >> 5;
    const int wm = (MODE == 0) ? (wid >> 3) : (wid >> 2);
    const int wn = (MODE == 0) ? (wid & 7) : (wid & 3);
    const int grp = lane >> 2, qid = lane & 3;
    const long row0 = (long)blockIdx.x * BM;

    // ---- X tile: rows as quad-interleaved rowpairs (r, r+8) ----
    {
        const int rp = tid >> 4, l = tid & 15;
        const int rA = (rp >> 3) * 16 + (rp & 7);
        const long gA = row0 + rA, gB = gA + 8;
        for (int c = l * 4; c < K; c += 64) {
            float4 va, vb;
            if (c < KA) {
                va = *(const float4*)(srcA + gA * lda + c);
                vb = *(const float4*)(srcA + gB * lda + c);
            } else {
                va = *(const float4*)(srcB + gA * 512 + (c - KA));
                vb = *(const float4*)(srcB + gB * 512 + (c - KA));
            }
            unsigned* base = xs + rp * XP + ((c >> 3) << 4) + (((c >> 2) & 1) << 1);
            *(uint2*)(base + 0)  = make_uint2(f2tf32(va.x), f2tf32(vb.x));
            *(uint2*)(base + 4)  = make_uint2(f2tf32(va.y), f2tf32(vb.y));
            *(uint2*)(base + 8)  = make_uint2(f2tf32(va.z), f2tf32(vb.z));
            *(uint2*)(base + 12) = make_uint2(f2tf32(va.w), f2tf32(vb.w));
        }
    }

    int aOff[MT];
    #pragma unroll
    for (int mt = 0; mt < MT; mt++)
        aOff[mt] = ((wm * MT + mt) * 8 + grp) * XP + qid * 4;
    const int bOff = (wn * 8 + grp) * 16 + qid * 4;
    const unsigned swbase = (unsigned)__cvta_generic_to_shared(wsm);

    for (int ni = 0; ni < NITER; ni++) {
        float acc[4][MT][2][4];
        #pragma unroll
        for (int g = 0; g < 4; g++)
            #pragma unroll
            for (int mt = 0; mt < MT; mt++)
                #pragma unroll
                for (int nt = 0; nt < 2; nt++)
                    #pragma unroll
                    for (int e = 0; e < 4; e++) acc[g][mt][nt][e] = 0.f;

        const unsigned* gw = g_wpack + wbase + (size_t)ni * NS * WSTG;

        auto issue = [&](int s) {
            if (s < NS) {
                const unsigned* src = gw + (size_t)s * WSTG + tid * CPW;
                unsigned sa = swbase + (unsigned)(((s & 1) * WSTG + tid * CPW) * 4);
                #pragma unroll
                for (int j = 0; j < CPW / 4; j++)
                    asm volatile("cp.async.cg.shared.global [%0], [%1], 16;"
                                 :: "r"(sa + j * 16), "l"(src + j * 4));
            }
            asm volatile("cp.async.commit_group;");
        };

        issue(0); issue(1);

        for (int s = 0; s < NS; s++) {
            asm volatile("cp.async.wait_group 1;");
            __syncthreads();
            const unsigned* wb = wsm + (s & 1) * WSTG;
            #pragma unroll
            for (int h = 0; h < 2; h++) {
                uint4 a[MT];
                #pragma unroll
                for (int mt = 0; mt < MT; mt++)
                    a[mt] = *(const uint4*)(xs + aOff[mt] + s * 32 + h * 16);
                #pragma unroll
                for (int g = 0; g < 4; g++) {
                    uint4 bq = *(const uint4*)(wb + h * (WSTG / 2) + g * GSTG + bOff);
                    unsigned bf0[2] = {bq.x, bq.y}, bf1[2] = {bq.z, bq.w};
                    #pragma unroll
                    for (int mt = 0; mt < MT; mt++) {
                        mma8(acc[g][mt][0], (const unsigned*)&a[mt], bf0);
                        mma8(acc[g][mt][1], (const unsigned*)&a[mt], bf1);
                    }
                }
            }
            __syncthreads();
            issue(s + 2);
        }

        // ---- epilogue ----
        if (MODE == 0) {
            #pragma unroll
            for (int mt = 0; mt < MT; mt++)
                #pragma unroll
                for (int rh = 0; rh < 2; rh++) {
                    const long gRow = row0 + wm * 32 + mt * 16 + grp + rh * 8;
                    const int e = rh * 2;
                    #pragma unroll
                    for (int nt = 0; nt < 2; nt++) {
                        const int n = ni * 128 + wn * 16 + nt * 8 + 2 * qid;
                        float2 vb;
                        vb = *(const float2*)&b0[n];
                        float pf0 = acc[0][mt][nt][e] + vb.x, pf1 = acc[0][mt][nt][e + 1] + vb.y;
                        vb = *(const float2*)&b1[n];
                        float pk0 = acc[1][mt][nt][e] + vb.x, pk1 = acc[1][mt][nt][e + 1] + vb.y;
                        vb = *(const float2*)&b2[n];
                        float pi0 = acc[2][mt][nt][e] + vb.x, pi1 = acc[2][mt][nt][e + 1] + vb.y;
                        vb = *(const float2*)&b3[n];
                        float ps0 = acc[3][mt][nt][e] + vb.x, ps1 = acc[3][mt][nt][e + 1] + vb.y;
                        const float2 cold = *(const float2*)&state_in[gRow * 512 + 256 + n];
                        float cn0 = sigf(pf0) * cold.x + sigf(pk0) * tanhf(pi0);
                        float cn1 = sigf(pf1) * cold.y + sigf(pk1) * tanhf(pi1);
                        float o0 = sigf(ps0) * tanhf(cn0);
                        float o1 = sigf(ps1) * tanhf(cn1);
                        *(float2*)&new_state[gRow * 512 + n]       = make_float2(o0, o1);
                        *(float2*)&new_state[gRow * 512 + 256 + n] = make_float2(cn0, cn1);
                    }
                }
        } else {
            #pragma unroll
            for (int rh = 0; rh < 2; rh++) {
                const long gRow = row0 + wm * 16 + grp + rh * 8;
                const int e = rh * 2;
                #pragma unroll
                for (int nt = 0; nt < 2; nt++) {
                    const int ncl = wn * 16 + nt * 8 + 2 * qid;
                    if (ni == 0) {
                        #pragma unroll
                        for (int g = 0; g < 4; g++)
                            *(float2*)&means[gRow * 256 + g * 64 + ncl] =
                                make_float2(acc[g][0][nt][e], acc[g][0][nt][e + 1]);
                    } else if (ni == 1) {
                        #pragma unroll
                        for (int g = 0; g < 4; g++)
                            *(float2*)&devs[gRow * 256 + g * 64 + ncl] =
                                make_float2(__expf(acc[g][0][nt][e]),
                                            __expf(acc[g][0][nt][e + 1]));
                    } else {
                        float ex[4][2], inv[2];
                        #pragma unroll
                        for (int j = 0; j < 2; j++) {
                            float v0 = acc[0][0][nt][e + j], v1 = acc[1][0][nt][e + j];
                            float v2 = acc[2][0][nt][e + j], v3 = acc[3][0][nt][e + j];
                            float m = fmaxf(fmaxf(v0, v1), fmaxf(v2, v3));
                            ex[0][j] = __expf(v0 - m); ex[1][j] = __expf(v1 - m);
                            ex[2][j] = __expf(v2 - m); ex[3][j] = __expf(v3 - m);
                            inv[j] = 1.0f / (ex[0][j] + ex[1][j] + ex[2][j] + ex[3][j]);
                        }
                        #pragma unroll
                        for (int g = 0; g < 4; g++)
                            *(float2*)&mult[gRow * 256 + g * 64 + ncl] =
                                make_float2(ex[g][0] * inv[0], ex[g][1] * inv[1]);
                    }
                }
            }
        }
    }
}

extern "C" void kernel_launch(void* const* d_in, const int* in_sizes, int n_in,
                              void* d_out, int out_size)
{
    const float* inp    = (const float*)d_in[0];
    const float* state1 = (const float*)d_in[1];
    const float* state2 = (const float*)d_in[2];
    const float* ffw    = (const float*)d_in[19];
    const float *l1w[4], *l1b[4], *l2w[4], *l2b[4];

    if (in_sizes[5] == 512 * 256) {
        for (int g = 0; g < 4; g++) {           // dict insertion order
            l1w[g] = (const float*)d_in[3 + 4 * g];
            l1b[g] = (const float*)d_in[4 + 4 * g];
            l2w[g] = (const float*)d_in[5 + 4 * g];
            l2b[g] = (const float*)d_in[6 + 4 * g];
        }
    } else {
        for (int g = 0; g < 4; g++) {           // signature order
            l1w[g] = (const float*)d_in[3 + 2 * g];
            l1b[g] = (const float*)d_in[4 + 2 * g];
            l2w[g] = (const float*)d_in[11 + 2 * g];
            l2b[g] = (const float*)d_in[12 + 2 * g];
        }
    }

    float* outp  = (float*)d_out;
    float* means = outp;
    float* devs  = outp + (size_t)BATCH * 256;
    float* mult  = outp + (size_t)BATCH * 512;
    float* ns1   = outp + (size_t)BATCH * 768;
    float* ns2   = ns1  + (size_t)BATCH * 512;

    // pack totals: L1 2*20*8192 | L2 2*32*8192 | FF 3*16*4096
    const int W1 = 0,        S1 = 327680;
    const int W2 = S1,       S2 = 524288;
    const int WF = W2 + S2,  SF = 196608;

    pack_lstm<<<(S1 + 255) / 256, 256>>>(W1, l1w[0], l1w[1], l1w[2], l1w[3], 20, S1);
    pack_lstm<<<(S2 + 255) / 256, 256>>>(W2, l2w[0], l2w[1], l2w[2], l2w[3], 32, S2);
    pack_ff  <<<(SF + 255) / 256, 256>>>(WF, ffw, SF);

    const size_t sm1 = (size_t)(32 * (2 * 320 + 16) + 2 * 8192) * 4;  // 149504
    const size_t sm2 = (size_t)(32 * (2 * 512 + 16) + 2 * 8192) * 4;  // 198656
    const size_t sm3 = (size_t)(32 * (2 * 256 + 16) + 2 * 4096) * 4;  // 100352
    cudaFuncSetAttribute(fused_kernel<0>, cudaFuncAttributeMaxDynamicSharedMemorySize, (int)sm2);
    cudaFuncSetAttribute(fused_kernel<1>, cudaFuncAttributeMaxDynamicSharedMemorySize, (int)sm3);

    const int grid = BATCH / BM;   // 512

    // Layer 1: X = [inp(64) | state1[:, :256]], K=320, 20 k16 stages
    fused_kernel<0><<<grid, 512, sm1>>>(320, 20, 2, W1, 64, 64,
        inp, state1, l1b[0], l1b[1], l1b[2], l1b[3],
        state1, ns1, nullptr, nullptr, nullptr);

    // Layer 2: X = [out1 | state2[:, :256]], K=512, 32 stages
    fused_kernel<0><<<grid, 512, sm2>>>(512, 32, 2, W2, 256, 512,
        ns1, state2, l2b[0], l2b[1], l2b[2], l2b[3],
        state2, ns2, nullptr, nullptr, nullptr);

    // FF head: X = out2, K=256, 16 stages, 3 n-chunks (means/devs/softmax)
    fused_kernel<1><<<grid, 512, sm3>>>(256, 16, 3, WF, 1 << 30, 512,
        ns2, ns2, nullptr, nullptr, nullptr, nullptr,
        nullptr, nullptr, means, devs, mult);
}

// round 15
// speedup vs baseline: 1.1721x; 1.1721x over previous
#include <cuda_runtime.h>
#include <math.h>
#include <stdint.h>

#define BATCH 32768
#define BM 64

// Pre-packed tf32 weights, fragment-quad-interleaved, k8-stage stream:
// LSTM: [ni][s8][g][cp64][q][e4]  (stage = 4096 words)
// FF:   [ni][s8][g][cp32][q][e4]  (stage = 2048 words)
__device__ __align__(1024) unsigned g_wpack[1048576];

__device__ __forceinline__ unsigned f2tf32(float v) {
    unsigned r;
    asm("cvt.rna.tf32.f32 %0, %1;" : "=r"(r) : "f"(v));
    return r;
}
__device__ __forceinline__ void mma8(float* d, const unsigned* a, const unsigned* b) {
    asm volatile(
        "mma.sync.aligned.m16n8k8.row.col.f32.tf32.tf32.f32 "
        "{%0,%1,%2,%3}, {%4,%5,%6,%7}, {%8,%9}, {%0,%1,%2,%3};\n"
        : "+f"(d[0]), "+f"(d[1]), "+f"(d[2]), "+f"(d[3])
        : "r"(a[0]), "r"(a[1]), "r"(a[2]), "r"(a[3]), "r"(b[0]), "r"(b[1]));
}
__device__ __forceinline__ float sigf(float x) { return 1.0f / (1.0f + __expf(-x)); }

// ---------- pack kernels: fp32 -> tf32(RNA), MMA-fragment quad layout ----------
__global__ void pack_lstm(int dst, const float* __restrict__ w0, const float* __restrict__ w1,
                          const float* __restrict__ w2, const float* __restrict__ w3,
                          int NS, int total)
{
    int t = blockIdx.x * 256 + threadIdx.x;
    if (t >= total) return;
    int e = t & 3, q = (t >> 2) & 3, cp = (t >> 4) & 63, g = (t >> 10) & 3, half = (t >> 12) & 1;
    int r = t >> 13, s = r % NS, ni = r / NS;
    int col = ni * 128 + (cp >> 3) * 16 + (cp & 7) + ((e >> 1) << 3);
    int k = s * 16 + half * 8 + q + ((e & 1) << 2);
    const float* w = (g == 0) ? w0 : (g == 1) ? w1 : (g == 2) ? w2 : w3;
    g_wpack[dst + t] = f2tf32(w[(long)k * 256 + col]);
}
__global__ void pack_ff(int dst, const float* __restrict__ fw, int total)
{
    int t = blockIdx.x * 256 + threadIdx.x;
    if (t >= total) return;
    int e = t & 3, q = (t >> 2) & 3, cp = (t >> 4) & 31, g = (t >> 9) & 3, half = (t >> 11) & 1;
    int r = t >> 12, s = r & 15, ni = r >> 4;
    int col = ni * 256 + g * 64 + (cp >> 3) * 16 + (cp & 7) + ((e >> 1) << 3);
    int k = s * 16 + half * 8 + q + ((e & 1) << 2);
    g_wpack[dst + t] = f2tf32(fw[(long)k * 768 + col]);
}

// MODE 0: LSTM layer (16 warps 2m x 8n, warp tile m32 x n16 x 4 gates)
// MODE 1: FF head    (16 warps 4m x 4n, warp tile m16 x n16 x 4 heads)
template <int MODE>
__global__ void __launch_bounds__(512, 1)
fused_kernel(int K, int NS, int NITER, int wbase, int KA, int lda,
             const float* __restrict__ srcA, const float* __restrict__ srcB,
             const float* __restrict__ b0, const float* __restrict__ b1,
             const float* __restrict__ b2, const float* __restrict__ b3,
             const float* __restrict__ state_in, float* __restrict__ new_state,
             float* __restrict__ means, float* __restrict__ devs,
             float* __restrict__ mult)
{
    constexpr int MT   = (MODE == 0) ? 2 : 1;
    constexpr int WSTG = (MODE == 0) ? 4096 : 2048;   // words per k8 stage
    constexpr int GSTG = (MODE == 0) ? 1024 : 512;    // words per gate per k8
    constexpr int CPW  = WSTG / 512;                  // words copied per thread

    extern __shared__ unsigned sm[];
    const int XP = 2 * K + 16;            // X pitch per rowpair (== 16 mod 32 words)
    unsigned* xs  = sm;                   // X: [rp=32][XP]
    unsigned* wsm = sm + 32 * XP;         // W ring: 4 x WSTG

    const int tid  = threadIdx.x;
    const int lane = tid & 31, wid = tid >> 5;
    const int wm = (MODE == 0) ? (wid >> 3) : (wid >> 2);
    const int wn = (MODE == 0) ? (wid & 7) : (wid & 3);
    const int grp = lane >> 2, qid = lane & 3;
    const long row0 = (long)blockIdx.x * BM;

    // ---- X tile: rows as quad-interleaved rowpairs (r, r+8) ----
    {
        const int rp = tid >> 4, l = tid & 15;
        const int rA = (rp >> 3) * 16 + (rp & 7);
        const long gA = row0 + rA, gB = gA + 8;
        for (int c = l * 4; c < K; c += 64) {
            float4 va, vb;
            if (c < KA) {
                va = *(const float4*)(srcA + gA * lda + c);
                vb = *(const float4*)(srcA + gB * lda + c);
            } else {
                va = *(const float4*)(srcB + gA * 512 + (c - KA));
                vb = *(const float4*)(srcB + gB * 512 + (c - KA));
            }
            unsigned* base = xs + rp * XP + ((c >> 3) << 4) + (((c >> 2) & 1) << 1);
            *(uint2*)(base + 0)  = make_uint2(f2tf32(va.x), f2tf32(vb.x));
            *(uint2*)(base + 4)  = make_uint2(f2tf32(va.y), f2tf32(vb.y));
            *(uint2*)(base + 8)  = make_uint2(f2tf32(va.z), f2tf32(vb.z));
            *(uint2*)(base + 12) = make_uint2(f2tf32(va.w), f2tf32(vb.w));
        }
    }

    int aOff[MT];
    #pragma unroll
    for (int mt = 0; mt < MT; mt++)
        aOff[mt] = ((wm * MT + mt) * 8 + grp) * XP + qid * 4;
    const int bOff = (wn * 8 + grp) * 16 + qid * 4;
    const unsigned swbase = (unsigned)__cvta_generic_to_shared(wsm);
    const unsigned* gw = g_wpack + wbase;
    const int TOT = NITER * NS;

    auto issue = [&](int s) {
        if (s < TOT) {
            const unsigned* src = gw + (size_t)s * WSTG + tid * CPW;
            unsigned sa = swbase + (unsigned)(((s & 3) * WSTG + tid * CPW) * 4);
            #pragma unroll
            for (int j = 0; j < CPW / 4; j++)
                asm volatile("cp.async.cg.shared.global [%0], [%1], 16;"
                             :: "r"(sa + j * 16), "l"(src + j * 4));
        }
        asm volatile("cp.async.commit_group;");
    };

    issue(0); issue(1); issue(2);

    float acc[4][MT][2][4];
    #pragma unroll
    for (int g = 0; g < 4; g++)
        #pragma unroll
        for (int mt = 0; mt < MT; mt++)
            #pragma unroll
            for (int nt = 0; nt < 2; nt++)
                #pragma unroll
                for (int e = 0; e < 4; e++) acc[g][mt][nt][e] = 0.f;

    int ni = 0, koff = 0;

    for (int ts = 0; ts < TOT; ts++) {
        asm volatile("cp.async.wait_group 2;");
        __syncthreads();
        const unsigned* wb = wsm + (ts & 3) * WSTG;

        uint4 a[MT];
        #pragma unroll
        for (int mt = 0; mt < MT; mt++)
            a[mt] = *(const uint4*)(xs + aOff[mt] + koff);
        #pragma unroll
        for (int g = 0; g < 4; g++) {
            uint4 bq = *(const uint4*)(wb + g * GSTG + bOff);
            unsigned bf0[2] = {bq.x, bq.y}, bf1[2] = {bq.z, bq.w};
            #pragma unroll
            for (int mt = 0; mt < MT; mt++) {
                mma8(acc[g][mt][0], (const unsigned*)&a[mt], bf0);
                mma8(acc[g][mt][1], (const unsigned*)&a[mt], bf1);
            }
        }
        issue(ts + 3);
        koff += 16;

        if (koff == NS * 16) {
            // ---- group epilogue (register-only; W prefetch continues async) ----
            if (MODE == 0) {
                #pragma unroll
                for (int mt = 0; mt < MT; mt++)
                    #pragma unroll
                    for (int rh = 0; rh < 2; rh++) {
                        const long gRow = row0 + wm * 32 + mt * 16 + grp + rh * 8;
                        const int e = rh * 2;
                        #pragma unroll
                        for (int nt = 0; nt < 2; nt++) {
                            const int n = ni * 128 + wn * 16 + nt * 8 + 2 * qid;
                            float2 vb;
                            vb = *(const float2*)&b0[n];
                            float pf0 = acc[0][mt][nt][e] + vb.x, pf1 = acc[0][mt][nt][e + 1] + vb.y;
                            vb = *(const float2*)&b1[n];
                            float pk0 = acc[1][mt][nt][e] + vb.x, pk1 = acc[1][mt][nt][e + 1] + vb.y;
                            vb = *(const float2*)&b2[n];
                            float pi0 = acc[2][mt][nt][e] + vb.x, pi1 = acc[2][mt][nt][e + 1] + vb.y;
                            vb = *(const float2*)&b3[n];
                            float ps0 = acc[3][mt][nt][e] + vb.x, ps1 = acc[3][mt][nt][e + 1] + vb.y;
                            const float2 cold = *(const float2*)&state_in[gRow * 512 + 256 + n];
                            float cn0 = sigf(pf0) * cold.x + sigf(pk0) * tanhf(pi0);
                            float cn1 = sigf(pf1) * cold.y + sigf(pk1) * tanhf(pi1);
                            float o0 = sigf(ps0) * tanhf(cn0);
                            float o1 = sigf(ps1) * tanhf(cn1);
                            *(float2*)&new_state[gRow * 512 + n]       = make_float2(o0, o1);
                            *(float2*)&new_state[gRow * 512 + 256 + n] = make_float2(cn0, cn1);
                        }
                    }
            } else {
                #pragma unroll
                for (int rh = 0; rh < 2; rh++) {
                    const long gRow = row0 + wm * 16 + grp + rh * 8;
                    const int e = rh * 2;
                    #pragma unroll
                    for (int nt = 0; nt < 2; nt++) {
                        const int ncl = wn * 16 + nt * 8 + 2 * qid;
                        if (ni == 0) {
                            #pragma unroll
                            for (int g = 0; g < 4; g++)
                                *(float2*)&means[gRow * 256 + g * 64 + ncl] =
                                    make_float2(acc[g][0][nt][e], acc[g][0][nt][e + 1]);
                        } else if (ni == 1) {
                            #pragma unroll
                            for (int g = 0; g < 4; g++)
                                *(float2*)&devs[gRow * 256 + g * 64 + ncl] =
                                    make_float2(__expf(acc[g][0][nt][e]),
                                                __expf(acc[g][0][nt][e + 1]));
                        } else {
                            float ex[4][2], inv[2];
                            #pragma unroll
                            for (int j = 0; j < 2; j++) {
                                float v0 = acc[0][0][nt][e + j], v1 = acc[1][0][nt][e + j];
                                float v2 = acc[2][0][nt][e + j], v3 = acc[3][0][nt][e + j];
                                float m = fmaxf(fmaxf(v0, v1), fmaxf(v2, v3));
                                ex[0][j] = __expf(v0 - m); ex[1][j] = __expf(v1 - m);
                                ex[2][j] = __expf(v2 - m); ex[3][j] = __expf(v3 - m);
                                inv[j] = 1.0f / (ex[0][j] + ex[1][j] + ex[2][j] + ex[3][j]);
                            }
                            #pragma unroll
                            for (int g = 0; g < 4; g++)
                                *(float2*)&mult[gRow * 256 + g * 64 + ncl] =
                                    make_float2(ex[g][0] * inv[0], ex[g][1] * inv[1]);
                        }
                    }
                }
            }
            koff = 0;
            ni++;
            #pragma unroll
            for (int g = 0; g < 4; g++)
                #pragma unroll
                for (int mt = 0; mt < MT; mt++)
                    #pragma unroll
                    for (int nt = 0; nt < 2; nt++)
                        #pragma unroll
                        for (int e = 0; e < 4; e++) acc[g][mt][nt][e] = 0.f;
        }
    }
}

extern "C" void kernel_launch(void* const* d_in, const int* in_sizes, int n_in,
                              void* d_out, int out_size)
{
    const float* inp    = (const float*)d_in[0];
    const float* state1 = (const float*)d_in[1];
    const float* state2 = (const float*)d_in[2];
    const float* ffw    = (const float*)d_in[19];
    const float *l1w[4], *l1b[4], *l2w[4], *l2b[4];

    if (in_sizes[5] == 512 * 256) {
        for (int g = 0; g < 4; g++) {           // dict insertion order
            l1w[g] = (const float*)d_in[3 + 4 * g];
            l1b[g] = (const float*)d_in[4 + 4 * g];
            l2w[g] = (const float*)d_in[5 + 4 * g];
            l2b[g] = (const float*)d_in[6 + 4 * g];
        }
    } else {
        for (int g = 0; g < 4; g++) {           // signature order
            l1w[g] = (const float*)d_in[3 + 2 * g];
            l1b[g] = (const float*)d_in[4 + 2 * g];
            l2w[g] = (const float*)d_in[11 + 2 * g];
            l2b[g] = (const float*)d_in[12 + 2 * g];
        }
    }

    float* outp  = (float*)d_out;
    float* means = outp;
    float* devs  = outp + (size_t)BATCH * 256;
    float* mult  = outp + (size_t)BATCH * 512;
    float* ns1   = outp + (size_t)BATCH * 768;
    float* ns2   = ns1  + (size_t)BATCH * 512;

    const int W1 = 0,        S1 = 327680;
    const int W2 = S1,       S2 = 524288;
    const int WF = W2 + S2,  SF = 196608;

    pack_lstm<<<(S1 + 255) / 256, 256>>>(W1, l1w[0], l1w[1], l1w[2], l1w[3], 20, S1);
    pack_lstm<<<(S2 + 255) / 256, 256>>>(W2, l2w[0], l2w[1], l2w[2], l2w[3], 32, S2);
    pack_ff  <<<(SF + 255) / 256, 256>>>(WF, ffw, SF);

    const size_t sm1 = (size_t)(32 * (2 * 320 + 16) + 4 * 4096) * 4;  // 149504
    const size_t sm2 = (size_t)(32 * (2 * 512 + 16) + 4 * 4096) * 4;  // 198656
    const size_t sm3 = (size_t)(32 * (2 * 256 + 16) + 4 * 2048) * 4;  // 100352
    cudaFuncSetAttribute(fused_kernel<0>, cudaFuncAttributeMaxDynamicSharedMemorySize, (int)sm2);
    cudaFuncSetAttribute(fused_kernel<1>, cudaFuncAttributeMaxDynamicSharedMemorySize, (int)sm3);

    const int grid = BATCH / BM;   // 512

    // Layer 1: X = [inp(64) | state1[:, :256]], K=320, 40 k8 stages/group
    fused_kernel<0><<<grid, 512, sm1>>>(320, 40, 2, W1, 64, 64,
        inp, state1, l1b[0], l1b[1], l1b[2], l1b[3],
        state1, ns1, nullptr, nullptr, nullptr);

    // Layer 2: X = [out1 | state2[:, :256]], K=512, 64 stages/group
    fused_kernel<0><<<grid, 512, sm2>>>(512, 64, 2, W2, 256, 512,
        ns1, state2, l2b[0], l2b[1], l2b[2], l2b[3],
        state2, ns2, nullptr, nullptr, nullptr);

    // FF head: X = out2, K=256, 32 stages/group, 3 groups (means/devs/softmax)
    fused_kernel<1><<<grid, 512, sm3>>>(256, 32, 3, WF, 1 << 30, 512,
        ns2, ns2, nullptr, nullptr, nullptr, nullptr,
        nullptr, nullptr, means, devs, mult);
}

// round 16
// speedup vs baseline: 1.8630x; 1.5895x over previous
#include <cuda_runtime.h>
#include <cuda_fp16.h>
#include <math.h>
#include <stdint.h>

#define BATCH 32768
#define BM 64

// Pre-packed fp16 weights (half2 words), MMA-fragment layout, k16-stage stream:
// LSTM: [ni][s16][g][cg][cp][q][w]  (stage = 4096 words = 16KB)
// FF:   [ni][s16][g][cg][cp][q][w]  (stage = 2048 words =  8KB)
__device__ __align__(1024) unsigned g_wpack[524288];

__device__ __forceinline__ void mma16(float* d, const unsigned* a, const unsigned* b) {
    asm volatile(
        "mma.sync.aligned.m16n8k16.row.col.f32.f16.f16.f32 "
        "{%0,%1,%2,%3}, {%4,%5,%6,%7}, {%8,%9}, {%0,%1,%2,%3};\n"
        : "+f"(d[0]), "+f"(d[1]), "+f"(d[2]), "+f"(d[3])
        : "r"(a[0]), "r"(a[1]), "r"(a[2]), "r"(a[3]), "r"(b[0]), "r"(b[1]));
}
__device__ __forceinline__ float sigf(float x) { return 1.0f / (1.0f + __expf(-x)); }
__device__ __forceinline__ unsigned h2u(float lo, float hi) {
    __half2 h = __floats2half2_rn(lo, hi);
    return *(unsigned*)&h;
}

// ---------- pack kernels: fp32 -> fp16, m16n8k16 B-fragment layout ----------
// word w at [g][cg][cp][q]: w0=(k=2q..2q+1, n=cg*16+cp) w1=(k+8, n) w2=(k01, n+8) w3=(k89, n+8)
__global__ void pack_lstm(int dst, const float* __restrict__ w0, const float* __restrict__ w1,
                          const float* __restrict__ w2, const float* __restrict__ w3,
                          int NS16, int total)
{
    int t = blockIdx.x * 256 + threadIdx.x;
    if (t >= total) return;
    int w = t & 3, q = (t >> 2) & 3, cp = (t >> 4) & 7, cg = (t >> 7) & 7, g = (t >> 10) & 3;
    int r = t >> 12, s = r % NS16, ni = r / NS16;
    int k = s * 16 + 2 * q + (w & 1) * 8;
    int col = ni * 128 + cg * 16 + cp + ((w >> 1) << 3);
    const float* wp = (g == 0) ? w0 : (g == 1) ? w1 : (g == 2) ? w2 : w3;
    g_wpack[dst + t] = h2u(wp[(long)k * 256 + col], wp[(long)(k + 1) * 256 + col]);
}
__global__ void pack_ff(int dst, const float* __restrict__ fw, int total)
{
    int t = blockIdx.x * 256 + threadIdx.x;
    if (t >= total) return;
    int w = t & 3, q = (t >> 2) & 3, cp = (t >> 4) & 7, cg = (t >> 7) & 3, g = (t >> 9) & 3;
    int s = (t >> 11) & 15, ni = t >> 15;
    int k = s * 16 + 2 * q + (w & 1) * 8;
    int col = ni * 256 + g * 64 + cg * 16 + cp + ((w >> 1) << 3);
    g_wpack[dst + t] = h2u(fw[(long)k * 768 + col], fw[(long)(k + 1) * 768 + col]);
}

// MODE 0: LSTM layer (16 warps 2m x 8n, warp tile m32 x n16 x 4 gates)
// MODE 1: FF head    (16 warps 4m x 4n, warp tile m16 x n16 x 4 heads)
template <int MODE>
__global__ void __launch_bounds__(512, 1)
fused_kernel(int K, int NS16, int NITER, int wbase, int KA, int lda,
             const float* __restrict__ srcA, const float* __restrict__ srcB,
             const float* __restrict__ b0, const float* __restrict__ b1,
             const float* __restrict__ b2, const float* __restrict__ b3,
             const float* __restrict__ state_in, float* __restrict__ new_state,
             float* __restrict__ means, float* __restrict__ devs,
             float* __restrict__ mult)
{
    constexpr int MT   = (MODE == 0) ? 2 : 1;
    constexpr int WSTG = (MODE == 0) ? 4096 : 2048;   // words per k16 stage
    constexpr int GSTG = (MODE == 0) ? 1024 : 512;    // words per gate per stage
    constexpr int CPW  = WSTG / 512;                  // words copied per thread (8 / 4)

    extern __shared__ unsigned sm[];
    const int XP = K + 16;                // X words per rowpair (== 16 mod 32)
    unsigned* xs  = sm;                   // X: [rp=32][XP] (half2 words)
    unsigned* wsm = sm + 32 * XP;         // W ring: 8 x WSTG

    const int tid  = threadIdx.x;
    const int lane = tid & 31, wid = tid >> 5;
    const int wm = (MODE == 0) ? (wid >> 3) : (wid >> 2);
    const int wn = (MODE == 0) ? (wid & 7) : (wid & 3);
    const int grp = lane >> 2, qid = lane & 3;
    const long row0 = (long)blockIdx.x * BM;

    // ---- X tile: fp16, rowpair (r, r+8), per k16 block: [q][w4] fragment words ----
    {
        const int rp = tid >> 4, l = tid & 15;
        const int rA = (rp >> 3) * 16 + (rp & 7);
        const long gA = row0 + rA, gB = gA + 8;
        for (int c = l * 4; c < K; c += 64) {
            float4 va, vb;
            if (c < KA) {
                va = *(const float4*)(srcA + gA * lda + c);
                vb = *(const float4*)(srcA + gB * lda + c);
            } else {
                va = *(const float4*)(srcB + gA * 512 + (c - KA));
                vb = *(const float4*)(srcB + gB * 512 + (c - KA));
            }
            int kb = c >> 4, p0 = (c & 15) >> 1;            // p0 in {0,2,4,6}
            int off = (p0 & 3) * 4 + ((p0 >> 2) << 1);
            unsigned* base = xs + rp * XP + kb * 16 + off;
            *(uint2*)(base)     = make_uint2(h2u(va.x, va.y), h2u(vb.x, vb.y));
            *(uint2*)(base + 4) = make_uint2(h2u(va.z, va.w), h2u(vb.z, vb.w));
        }
    }

    int aOff[MT];
    #pragma unroll
    for (int mt = 0; mt < MT; mt++)
        aOff[mt] = ((wm * MT + mt) * 8 + grp) * XP + qid * 4;
    const int bOff = (wn * 8 + grp) * 16 + qid * 4;
    const unsigned swbase = (unsigned)__cvta_generic_to_shared(wsm);
    const unsigned* gw = g_wpack + wbase;
    const int TOT = NITER * NS16;

    auto issue = [&](int s) {
        if (s < TOT) {
            const unsigned* src = gw + (size_t)s * WSTG + tid * CPW;
            unsigned sa = swbase + (unsigned)(((s & 7) * WSTG + tid * CPW) * 4);
            #pragma unroll
            for (int j = 0; j < CPW / 4; j++)
                asm volatile("cp.async.cg.shared.global [%0], [%1], 16;"
                             :: "r"(sa + j * 16), "l"(src + j * 4));
        }
        asm volatile("cp.async.commit_group;");
    };

    issue(0); issue(1); issue(2); issue(3); issue(4); issue(5); issue(6);

    float acc[4][MT][2][4];
    #pragma unroll
    for (int g = 0; g < 4; g++)
        #pragma unroll
        for (int mt = 0; mt < MT; mt++)
            #pragma unroll
            for (int nt = 0; nt < 2; nt++)
                #pragma unroll
                for (int e = 0; e < 4; e++) acc[g][mt][nt][e] = 0.f;

    int ni = 0, koff = 0;

    for (int ts = 0; ts < TOT; ts++) {
        asm volatile("cp.async.wait_group 6;");
        __syncthreads();
        const unsigned* wb = wsm + (ts & 7) * WSTG;

        uint4 a[MT];
        #pragma unroll
        for (int mt = 0; mt < MT; mt++)
            a[mt] = *(const uint4*)(xs + aOff[mt] + koff);
        #pragma unroll
        for (int g = 0; g < 4; g++) {
            uint4 bq = *(const uint4*)(wb + g * GSTG + bOff);
            unsigned bf0[2] = {bq.x, bq.y}, bf1[2] = {bq.z, bq.w};
            #pragma unroll
            for (int mt = 0; mt < MT; mt++) {
                mma16(acc[g][mt][0], (const unsigned*)&a[mt], bf0);
                mma16(acc[g][mt][1], (const unsigned*)&a[mt], bf1);
            }
        }
        issue(ts + 7);
        koff += 16;

        if (koff == NS16 * 16) {
            // ---- group epilogue (register-only; W prefetch continues async) ----
            if (MODE == 0) {
                #pragma unroll
                for (int mt = 0; mt < MT; mt++)
                    #pragma unroll
                    for (int rh = 0; rh < 2; rh++) {
                        const long gRow = row0 + wm * 32 + mt * 16 + grp + rh * 8;
                        const int e = rh * 2;
                        #pragma unroll
                        for (int nt = 0; nt < 2; nt++) {
                            const int n = ni * 128 + wn * 16 + nt * 8 + 2 * qid;
                            float2 vb;
                            vb = *(const float2*)&b0[n];
                            float pf0 = acc[0][mt][nt][e] + vb.x, pf1 = acc[0][mt][nt][e + 1] + vb.y;
                            vb = *(const float2*)&b1[n];
                            float pk0 = acc[1][mt][nt][e] + vb.x, pk1 = acc[1][mt][nt][e + 1] + vb.y;
                            vb = *(const float2*)&b2[n];
                            float pi0 = acc[2][mt][nt][e] + vb.x, pi1 = acc[2][mt][nt][e + 1] + vb.y;
                            vb = *(const float2*)&b3[n];
                            float ps0 = acc[3][mt][nt][e] + vb.x, ps1 = acc[3][mt][nt][e + 1] + vb.y;
                            const float2 cold = *(const float2*)&state_in[gRow * 512 + 256 + n];
                            float cn0 = sigf(pf0) * cold.x + sigf(pk0) * tanhf(pi0);
                            float cn1 = sigf(pf1) * cold.y + sigf(pk1) * tanhf(pi1);
                            float o0 = sigf(ps0) * tanhf(cn0);
                            float o1 = sigf(ps1) * tanhf(cn1);
                            *(float2*)&new_state[gRow * 512 + n]       = make_float2(o0, o1);
                            *(float2*)&new_state[gRow * 512 + 256 + n] = make_float2(cn0, cn1);
                        }
                    }
            } else {
                #pragma unroll
                for (int rh = 0; rh < 2; rh++) {
                    const long gRow = row0 + wm * 16 + grp + rh * 8;
                    const int e = rh * 2;
                    #pragma unroll
                    for (int nt = 0; nt < 2; nt++) {
                        const int ncl = wn * 16 + nt * 8 + 2 * qid;
                        if (ni == 0) {
                            #pragma unroll
                            for (int g = 0; g < 4; g++)
                                *(float2*)&means[gRow * 256 + g * 64 + ncl] =
                                    make_float2(acc[g][0][nt][e], acc[g][0][nt][e + 1]);
                        } else if (ni == 1) {
                            #pragma unroll
                            for (int g = 0; g < 4; g++)
                                *(float2*)&devs[gRow * 256 + g * 64 + ncl] =
                                    make_float2(__expf(acc[g][0][nt][e]),
                                                __expf(acc[g][0][nt][e + 1]));
                        } else {
                            float ex[4][2], inv[2];
                            #pragma unroll
                            for (int j = 0; j < 2; j++) {
                                float v0 = acc[0][0][nt][e + j], v1 = acc[1][0][nt][e + j];
                                float v2 = acc[2][0][nt][e + j], v3 = acc[3][0][nt][e + j];
                                float m = fmaxf(fmaxf(v0, v1), fmaxf(v2, v3));
                                ex[0][j] = __expf(v0 - m); ex[1][j] = __expf(v1 - m);
                                ex[2][j] = __expf(v2 - m); ex[3][j] = __expf(v3 - m);
                                inv[j] = 1.0f / (ex[0][j] + ex[1][j] + ex[2][j] + ex[3][j]);
                            }
                            #pragma unroll
                            for (int g = 0; g < 4; g++)
                                *(float2*)&mult[gRow * 256 + g * 64 + ncl] =
                                    make_float2(ex[g][0] * inv[0], ex[g][1] * inv[1]);
                        }
                    }
                }
            }
            koff = 0;
            ni++;
            #pragma unroll
            for (int g = 0; g < 4; g++)
                #pragma unroll
                for (int mt = 0; mt < MT; mt++)
                    #pragma unroll
                    for (int nt = 0; nt < 2; nt++)
                        #pragma unroll
                        for (int e = 0; e < 4; e++) acc[g][mt][nt][e] = 0.f;
        }
    }
}

extern "C" void kernel_launch(void* const* d_in, const int* in_sizes, int n_in,
                              void* d_out, int out_size)
{
    const float* inp    = (const float*)d_in[0];
    const float* state1 = (const float*)d_in[1];
    const float* state2 = (const float*)d_in[2];
    const float* ffw    = (const float*)d_in[19];
    const float *l1w[4], *l1b[4], *l2w[4], *l2b[4];

    if (in_sizes[5] == 512 * 256) {
        for (int g = 0; g < 4; g++) {           // dict insertion order
            l1w[g] = (const float*)d_in[3 + 4 * g];
            l1b[g] = (const float*)d_in[4 + 4 * g];
            l2w[g] = (const float*)d_in[5 + 4 * g];
            l2b[g] = (const float*)d_in[6 + 4 * g];
        }
    } else {
        for (int g = 0; g < 4; g++) {           // signature order
            l1w[g] = (const float*)d_in[3 + 2 * g];
            l1b[g] = (const float*)d_in[4 + 2 * g];
            l2w[g] = (const float*)d_in[11 + 2 * g];
            l2b[g] = (const float*)d_in[12 + 2 * g];
        }
    }

    float* outp  = (float*)d_out;
    float* means = outp;
    float* devs  = outp + (size_t)BATCH * 256;
    float* mult  = outp + (size_t)BATCH * 512;
    float* ns1   = outp + (size_t)BATCH * 768;
    float* ns2   = ns1  + (size_t)BATCH * 512;

    // stream word offsets: L1 2*20*4096 | L2 2*32*4096 | FF 3*16*2048
    const int W1 = 0,        S1 = 163840;
    const int W2 = S1,       S2 = 262144;
    const int WF = W2 + S2,  SF = 98304;

    pack_lstm<<<(S1 + 255) / 256, 256>>>(W1, l1w[0], l1w[1], l1w[2], l1w[3], 20, S1);
    pack_lstm<<<(S2 + 255) / 256, 256>>>(W2, l2w[0], l2w[1], l2w[2], l2w[3], 32, S2);
    pack_ff  <<<(SF + 255) / 256, 256>>>(WF, ffw, SF);

    const size_t sm1 = (size_t)(32 * (320 + 16) + 8 * 4096) * 4;  // 174080
    const size_t sm2 = (size_t)(32 * (512 + 16) + 8 * 4096) * 4;  // 198656
    const size_t sm3 = (size_t)(32 * (256 + 16) + 8 * 2048) * 4;  // 100352
    cudaFuncSetAttribute(fused_kernel<0>, cudaFuncAttributeMaxDynamicSharedMemorySize, (int)sm2);
    cudaFuncSetAttribute(fused_kernel<1>, cudaFuncAttributeMaxDynamicSharedMemorySize, (int)sm3);

    const int grid = BATCH / BM;   // 512

    // Layer 1: X = [inp(64) | state1[:, :256]], K=320, 20 k16 stages/group
    fused_kernel<0><<<grid, 512, sm1>>>(320, 20, 2, W1, 64, 64,
        inp, state1, l1b[0], l1b[1], l1b[2], l1b[3],
        state1, ns1, nullptr, nullptr, nullptr);

    // Layer 2: X = [out1 | state2[:, :256]], K=512, 32 stages/group
    fused_kernel<0><<<grid, 512, sm2>>>(512, 32, 2, W2, 256, 512,
        ns1, state2, l2b[0], l2b[1], l2b[2], l2b[3],
        state2, ns2, nullptr, nullptr, nullptr);

    // FF head: X = out2, K=256, 16 stages/group, 3 groups (means/devs/softmax)
    fused_kernel<1><<<grid, 512, sm3>>>(256, 16, 3, WF, 1 << 30, 512,
        ns2, ns2, nullptr, nullptr, nullptr, nullptr,
        nullptr, nullptr, means, devs, mult);
}

// round 17
// speedup vs baseline: 2.1470x; 1.1524x over previous
#include <cuda_runtime.h>
#include <cuda_fp16.h>
#include <math.h>
#include <stdint.h>

#define BATCH 32768
#define BM 64

// Pre-packed fp16 weights (half2 words), wn-partitioned fragment layout:
// LSTM stage (k16) = 4096 words: [wn:8][g:4][grp:8][q:4][w:4]
// FF   stage (k16) = 2048 words: [wn:4][g:4][grp:8][q:4][w:4]
__device__ __align__(1024) unsigned g_wpack[524288];

__device__ __forceinline__ void mma16(float* d, const unsigned* a, const unsigned* b) {
    asm volatile(
        "mma.sync.aligned.m16n8k16.row.col.f32.f16.f16.f32 "
        "{%0,%1,%2,%3}, {%4,%5,%6,%7}, {%8,%9}, {%0,%1,%2,%3};\n"
        : "+f"(d[0]), "+f"(d[1]), "+f"(d[2]), "+f"(d[3])
        : "r"(a[0]), "r"(a[1]), "r"(a[2]), "r"(a[3]), "r"(b[0]), "r"(b[1]));
}
__device__ __forceinline__ float sigf(float x) { return 1.0f / (1.0f + __expf(-x)); }
__device__ __forceinline__ unsigned h2u(float lo, float hi) {
    __half2 h = __floats2half2_rn(lo, hi);
    return *(unsigned*)&h;
}

// ---------- pack kernels: fp32 -> fp16, wn-partitioned m16n8k16 B-fragment layout ----------
__global__ void pack_lstm(int dst, const float* __restrict__ w0, const float* __restrict__ w1,
                          const float* __restrict__ w2, const float* __restrict__ w3,
                          int NS16, int total)
{
    int t = blockIdx.x * 256 + threadIdx.x;
    if (t >= total) return;
    int w = t & 3, q = (t >> 2) & 3, grp = (t >> 4) & 7, g = (t >> 7) & 3, wn = (t >> 9) & 7;
    int r = t >> 12, s = r % NS16, ni = r / NS16;
    int k = s * 16 + 2 * q + (w & 1) * 8;
    int col = ni * 128 + wn * 16 + grp + ((w >> 1) << 3);
    const float* wp = (g == 0) ? w0 : (g == 1) ? w1 : (g == 2) ? w2 : w3;
    g_wpack[dst + t] = h2u(wp[(long)k * 256 + col], wp[(long)(k + 1) * 256 + col]);
}
__global__ void pack_ff(int dst, const float* __restrict__ fw, int total)
{
    int t = blockIdx.x * 256 + threadIdx.x;
    if (t >= total) return;
    int w = t & 3, q = (t >> 2) & 3, grp = (t >> 4) & 7, g = (t >> 7) & 3, wn = (t >> 9) & 3;
    int r = t >> 11, s = r & 15, ni = r >> 4;
    int k = s * 16 + 2 * q + (w & 1) * 8;
    int col = ni * 256 + g * 64 + wn * 16 + grp + ((w >> 1) << 3);
    g_wpack[dst + t] = h2u(fw[(long)k * 768 + col], fw[(long)(k + 1) * 768 + col]);
}

// MODE 0: LSTM layer (16 warps 2m x 8n; wn-pairs of 2 warps share a private W ring)
// MODE 1: FF head    (16 warps 4m x 4n; wn-quads of 4 warps share a private W ring)
template <int MODE>
__global__ void __launch_bounds__(512, 1)
fused_kernel(int K, int NS16, int NITER, int wbase, int KA, int lda,
             const float* __restrict__ srcA, const float* __restrict__ srcB,
             const float* __restrict__ b0, const float* __restrict__ b1,
             const float* __restrict__ b2, const float* __restrict__ b3,
             const float* __restrict__ state_in, float* __restrict__ new_state,
             float* __restrict__ means, float* __restrict__ devs,
             float* __restrict__ mult)
{
    constexpr int MT   = (MODE == 0) ? 2 : 1;
    constexpr int WSTG = (MODE == 0) ? 4096 : 2048;  // words per k16 stage
    constexpr int SHW  = (MODE == 0) ? 2 : 4;        // warps sharing a wn region
    constexpr int CPL  = (MODE == 0) ? 8 : 4;        // words copied per lane per stage
    constexpr int BCNT = SHW * 32;                   // named-barrier thread count

    extern __shared__ unsigned sm[];
    const int XP = K + 16;                // X words per rowpair (== 16 mod 32)
    unsigned* xs  = sm;                   // X: [rp=32][XP] (half2 words)
    unsigned* wsm = sm + 32 * XP;         // W rings: [wn][8 slots][512 words]

    const int tid  = threadIdx.x;
    const int lane = tid & 31, wid = tid >> 5;
    const int wm = (MODE == 0) ? (wid >> 3) : (wid >> 2);
    const int wn = (MODE == 0) ? (wid & 7) : (wid & 3);
    const int grp = lane >> 2, qid = lane & 3;
    const long row0 = (long)blockIdx.x * BM;

    // ---- X tile: fp16, rowpair (r, r+8), per k16 block: [q][w4] fragment words ----
    {
        const int rp = tid >> 4, l = tid & 15;
        const int rA = (rp >> 3) * 16 + (rp & 7);
        const long gA = row0 + rA, gB = gA + 8;
        for (int c = l * 4; c < K; c += 64) {
            float4 va, vb;
            if (c < KA) {
                va = *(const float4*)(srcA + gA * lda + c);
                vb = *(const float4*)(srcA + gB * lda + c);
            } else {
                va = *(const float4*)(srcB + gA * 512 + (c - KA));
                vb = *(const float4*)(srcB + gB * 512 + (c - KA));
            }
            int kb = c >> 4, p0 = (c & 15) >> 1;            // p0 in {0,2,4,6}
            int off = (p0 & 3) * 4 + ((p0 >> 2) << 1);
            unsigned* base = xs + rp * XP + kb * 16 + off;
            *(uint2*)(base)     = make_uint2(h2u(va.x, va.y), h2u(vb.x, vb.y));
            *(uint2*)(base + 4) = make_uint2(h2u(va.z, va.w), h2u(vb.z, vb.w));
        }
    }

    int aOff[MT];
    #pragma unroll
    for (int mt = 0; mt < MT; mt++)
        aOff[mt] = ((wm * MT + mt) * 8 + grp) * XP + qid * 4;
    const int bOff = grp * 16 + qid * 4;               // within warp's 512-word slab
    const unsigned* ring = wsm + wn * 4096;            // 8 slots x 512 words
    const unsigned swbase = (unsigned)__cvta_generic_to_shared(ring);
    const int cpOff = wm * (512 / SHW) + lane * CPL;   // this warp's copy share
    const unsigned* gw = g_wpack + wbase;
    const int TOT = NITER * NS16;
    const int barid = 1 + wn;

    auto issue = [&](int s) {
        if (s < TOT) {
            const unsigned* src = gw + (size_t)s * WSTG + wn * 512 + cpOff;
            unsigned sa = swbase + (unsigned)((((s & 7) << 9) + cpOff) * 4);
            #pragma unroll
            for (int j = 0; j < CPL / 4; j++)
                asm volatile("cp.async.cg.shared.global [%0], [%1], 16;"
                             :: "r"(sa + j * 16), "l"(src + j * 4));
        }
        asm volatile("cp.async.commit_group;");
    };

    issue(0); issue(1); issue(2); issue(3); issue(4); issue(5); issue(6);
    __syncthreads();   // X tile ready (also covers first ring writes ordering)

    float acc[4][MT][2][4];
    #pragma unroll
    for (int g = 0; g < 4; g++)
        #pragma unroll
        for (int mt = 0; mt < MT; mt++)
            #pragma unroll
            for (int nt = 0; nt < 2; nt++)
                #pragma unroll
                for (int e = 0; e < 4; e++) acc[g][mt][nt][e] = 0.f;

    int ni = 0, koff = 0;

    for (int ts = 0; ts < TOT; ts++) {
        asm volatile("cp.async.wait_group 6;");
        asm volatile("bar.sync %0, %1;" :: "r"(barid), "r"(BCNT) : "memory");
        const unsigned* wb = ring + ((ts & 7) << 9);

        uint4 a[MT];
        #pragma unroll
        for (int mt = 0; mt < MT; mt++)
            a[mt] = *(const uint4*)(xs + aOff[mt] + koff);
        #pragma unroll
        for (int g = 0; g < 4; g++) {
            uint4 bq = *(const uint4*)(wb + g * 128 + bOff);
            unsigned bf0[2] = {bq.x, bq.y}, bf1[2] = {bq.z, bq.w};
            #pragma unroll
            for (int mt = 0; mt < MT; mt++) {
                mma16(acc[g][mt][0], (const unsigned*)&a[mt], bf0);
                mma16(acc[g][mt][1], (const unsigned*)&a[mt], bf1);
            }
        }
        issue(ts + 7);
        koff += 16;

        if (koff == NS16 * 16) {
            // ---- group epilogue (register->global; W prefetch continues async) ----
            if (MODE == 0) {
                #pragma unroll
                for (int mt = 0; mt < MT; mt++)
                    #pragma unroll
                    for (int rh = 0; rh < 2; rh++) {
                        const long gRow = row0 + wm * 32 + mt * 16 + grp + rh * 8;
                        const int e = rh * 2;
                        #pragma unroll
                        for (int nt = 0; nt < 2; nt++) {
                            const int n = ni * 128 + wn * 16 + nt * 8 + 2 * qid;
                            float2 vb;
                            vb = *(const float2*)&b0[n];
                            float pf0 = acc[0][mt][nt][e] + vb.x, pf1 = acc[0][mt][nt][e + 1] + vb.y;
                            vb = *(const float2*)&b1[n];
                            float pk0 = acc[1][mt][nt][e] + vb.x, pk1 = acc[1][mt][nt][e + 1] + vb.y;
                            vb = *(const float2*)&b2[n];
                            float pi0 = acc[2][mt][nt][e] + vb.x, pi1 = acc[2][mt][nt][e + 1] + vb.y;
                            vb = *(const float2*)&b3[n];
                            float ps0 = acc[3][mt][nt][e] + vb.x, ps1 = acc[3][mt][nt][e + 1] + vb.y;
                            const float2 cold = *(const float2*)&state_in[gRow * 512 + 256 + n];
                            float cn0 = sigf(pf0) * cold.x + sigf(pk0) * tanhf(pi0);
                            float cn1 = sigf(pf1) * cold.y + sigf(pk1) * tanhf(pi1);
                            float o0 = sigf(ps0) * tanhf(cn0);
                            float o1 = sigf(ps1) * tanhf(cn1);
                            *(float2*)&new_state[gRow * 512 + n]       = make_float2(o0, o1);
                            *(float2*)&new_state[gRow * 512 + 256 + n] = make_float2(cn0, cn1);
                        }
                    }
            } else {
                #pragma unroll
                for (int rh = 0; rh < 2; rh++) {
                    const long gRow = row0 + wm * 16 + grp + rh * 8;
                    const int e = rh * 2;
                    #pragma unroll
                    for (int nt = 0; nt < 2; nt++) {
                        const int ncl = wn * 16 + nt * 8 + 2 * qid;
                        if (ni == 0) {
                            #pragma unroll
                            for (int g = 0; g < 4; g++)
                                *(float2*)&means[gRow * 256 + g * 64 + ncl] =
                                    make_float2(acc[g][0][nt][e], acc[g][0][nt][e + 1]);
                        } else if (ni == 1) {
                            #pragma unroll
                            for (int g = 0; g < 4; g++)
                                *(float2*)&devs[gRow * 256 + g * 64 + ncl] =
                                    make_float2(__expf(acc[g][0][nt][e]),
                                                __expf(acc[g][0][nt][e + 1]));
                        } else {
                            float ex[4][2], inv[2];
                            #pragma unroll
                            for (int j = 0; j < 2; j++) {
                                float v0 = acc[0][0][nt][e + j], v1 = acc[1][0][nt][e + j];
                                float v2 = acc[2][0][nt][e + j], v3 = acc[3][0][nt][e + j];
                                float m = fmaxf(fmaxf(v0, v1), fmaxf(v2, v3));
                                ex[0][j] = __expf(v0 - m); ex[1][j] = __expf(v1 - m);
                                ex[2][j] = __expf(v2 - m); ex[3][j] = __expf(v3 - m);
                                inv[j] = 1.0f / (ex[0][j] + ex[1][j] + ex[2][j] + ex[3][j]);
                            }
                            #pragma unroll
                            for (int g = 0; g < 4; g++)
                                *(float2*)&mult[gRow * 256 + g * 64 + ncl] =
                                    make_float2(ex[g][0] * inv[0], ex[g][1] * inv[1]);
                        }
                    }
                }
            }
            koff = 0;
            ni++;
            #pragma unroll
            for (int g = 0; g < 4; g++)
                #pragma unroll
                for (int mt = 0; mt < MT; mt++)
                    #pragma unroll
                    for (int nt = 0; nt < 2; nt++)
                        #pragma unroll
                        for (int e = 0; e < 4; e++) acc[g][mt][nt][e] = 0.f;
        }
    }
}

extern "C" void kernel_launch(void* const* d_in, const int* in_sizes, int n_in,
                              void* d_out, int out_size)
{
    const float* inp    = (const float*)d_in[0];
    const float* state1 = (const float*)d_in[1];
    const float* state2 = (const float*)d_in[2];
    const float* ffw    = (const float*)d_in[19];
    const float *l1w[4], *l1b[4], *l2w[4], *l2b[4];

    if (in_sizes[5] == 512 * 256) {
        for (int g = 0; g < 4; g++) {           // dict insertion order
            l1w[g] = (const float*)d_in[3 + 4 * g];
            l1b[g] = (const float*)d_in[4 + 4 * g];
            l2w[g] = (const float*)d_in[5 + 4 * g];
            l2b[g] = (const float*)d_in[6 + 4 * g];
        }
    } else {
        for (int g = 0; g < 4; g++) {           // signature order
            l1w[g] = (const float*)d_in[3 + 2 * g];
            l1b[g] = (const float*)d_in[4 + 2 * g];
            l2w[g] = (const float*)d_in[11 + 2 * g];
            l2b[g] = (const float*)d_in[12 + 2 * g];
        }
    }

    float* outp  = (float*)d_out;
    float* means = outp;
    float* devs  = outp + (size_t)BATCH * 256;
    float* mult  = outp + (size_t)BATCH * 512;
    float* ns1   = outp + (size_t)BATCH * 768;
    float* ns2   = ns1  + (size_t)BATCH * 512;

    // stream word offsets: L1 2*20*4096 | L2 2*32*4096 | FF 3*16*2048
    const int W1 = 0,        S1 = 163840;
    const int W2 = S1,       S2 = 262144;
    const int WF = W2 + S2,  SF = 98304;

    pack_lstm<<<(S1 + 255) / 256, 256>>>(W1, l1w[0], l1w[1], l1w[2], l1w[3], 20, S1);
    pack_lstm<<<(S2 + 255) / 256, 256>>>(W2, l2w[0], l2w[1], l2w[2], l2w[3], 32, S2);
    pack_ff  <<<(SF + 255) / 256, 256>>>(WF, ffw, SF);

    const size_t sm1 = (size_t)(32 * (320 + 16) + 8 * 4096) * 4;  // 174080
    const size_t sm2 = (size_t)(32 * (512 + 16) + 8 * 4096) * 4;  // 198656
    const size_t sm3 = (size_t)(32 * (256 + 16) + 4 * 4096) * 4;  // 100352
    cudaFuncSetAttribute(fused_kernel<0>, cudaFuncAttributeMaxDynamicSharedMemorySize, (int)sm2);
    cudaFuncSetAttribute(fused_kernel<1>, cudaFuncAttributeMaxDynamicSharedMemorySize, (int)sm3);

    const int grid = BATCH / BM;   // 512

    // Layer 1: X = [inp(64) | state1[:, :256]], K=320, 20 k16 stages/group
    fused_kernel<0><<<grid, 512, sm1>>>(320, 20, 2, W1, 64, 64,
        inp, state1, l1b[0], l1b[1], l1b[2], l1b[3],
        state1, ns1, nullptr, nullptr, nullptr);

    // Layer 2: X = [out1 | state2[:, :256]], K=512, 32 stages/group
    fused_kernel<0><<<grid, 512, sm2>>>(512, 32, 2, W2, 256, 512,
        ns1, state2, l2b[0], l2b[1], l2b[2], l2b[3],
        state2, ns2, nullptr, nullptr, nullptr);

    // FF head: X = out2, K=256, 16 stages/group, 3 groups (means/devs/softmax)
    fused_kernel<1><<<grid, 512, sm3>>>(256, 16, 3, WF, 1 << 30, 512,
        ns2, ns2, nullptr, nullptr, nullptr, nullptr,
        nullptr, nullptr, means, devs, mult);
}